// round 7
// baseline (speedup 1.0000x reference)
#include <cuda_runtime.h>

// FixedChannelDP: y[p, n] = sum_{k=0}^{512} h[k] * x[p, n-k]  (full conv, zero-padded)
// Output layout: [2, NOUT, 2] f32 == float2 (re, im) per sample.
//
// R6 (resubmitted after broker timeout): software-pipelined window loads
// (prefetch one full phase ahead, interleaved after slot death), h taps as
// pre-packed u64 LDS.64 operands, per-group h prefetch. Keeps: f32x2 FMAs,
// accA/accB complex split, bank-conflict-free SIDX padding, 3 CTAs/SM.

#define NTAPS   513
#define HALO    512
#define TILE    2048
#define THREADS 256
#define PT      8
#define XTILE   (TILE + HALO + 16)     // 2576: +16 prefetch tail (zero, never consumed)
#define XPHYS   (XTILE + XTILE / 8)    // 2898 with bank padding

#define SIDX(i) ((i) + ((i) >> 3))

typedef unsigned long long u64;

__device__ __forceinline__ u64 pack2(float lo, float hi) {
    u64 r;
    asm("mov.b64 %0, {%1, %2};" : "=l"(r) : "f"(lo), "f"(hi));
    return r;
}

__device__ __forceinline__ u64 fma2(u64 a, u64 b, u64 c) {
    u64 d;
    asm("fma.rn.f32x2 %0, %1, %2, %3;" : "=l"(d) : "l"(a), "l"(b), "l"(c));
    return d;
}

__device__ __forceinline__ float2 unpack2(u64 v) {
    float lo, hi;
    asm("mov.b64 {%0, %1}, %2;" : "=f"(lo), "=f"(hi) : "l"(v));
    return make_float2(lo, hi);
}

__global__ void __launch_bounds__(THREADS, 3)
conv_dp_kernel(const float* __restrict__ txr, const float* __restrict__ txi,
               const float* __restrict__ hre, const float* __restrict__ him,
               float2* __restrict__ out, int N, int NOUT)
{
    __shared__ float2 sx[XPHYS];     // (xr, xi), zero-padded, bank-padded
    __shared__ u64 sh_rr[NTAPS];     // packed (hr, hr)
    __shared__ u64 sh_ii[NTAPS];     // packed (hi, hi)

    const int pol = blockIdx.y;
    const int tileStart = blockIdx.x * TILE;
    const float* __restrict__ xr = txr + (size_t)pol * N;
    const float* __restrict__ xi = txi + (size_t)pol * N;

    for (int i = threadIdx.x; i < XTILE; i += THREADS) {
        int g = tileStart - HALO + i;
        float a = 0.0f, b = 0.0f;
        if ((unsigned)g < (unsigned)N) { a = xr[g]; b = xi[g]; }
        sx[SIDX(i)] = make_float2(a, b);
    }
    for (int k = threadIdx.x; k < NTAPS; k += THREADS) {
        float r = hre[k], m = him[k];
        sh_rr[k] = pack2(r, r);
        sh_ii[k] = pack2(m, m);
    }
    __syncthreads();

    const int base = threadIdx.x * PT;

    u64 accA[PT], accB[PT];   // accA = sum hr*(xr,xi), accB = sum hi*(xr,xi)
    u64 w[16];                // circular window: offset o lives in slot o & 15
#pragma unroll
    for (int j = 0; j < PT; j++) { accA[j] = pack2(0.0f, 0.0f); accB[j] = pack2(0.0f, 0.0f); }

    // Preload offsets 0..15 into slots 0..15.
#pragma unroll
    for (int u = 0; u < 16; u++) {
        float2 v = sx[SIDX(base + u)];
        w[u] = pack2(v.x, v.y);
    }

    // 64 phases of 8 taps (kk = 512-k). Phase p (l0 = 8p) consumes offsets
    // l0..l0+14 and prefetches offsets l0+16..l0+23 — each load issued right
    // after the FMA group where its destination slot dies (group t frees slot
    // (l0+t)&15). Unrolled x2 so slot indices are compile-time constants.
#pragma unroll 1
    for (int cc = 0; cc < 32; cc++) {
        const int l0 = 16 * cc;

        // ---- phase A: l0 mod 16 == 0 ----
        {
            const int kb = 512 - l0;
            u64 hrr = sh_rr[kb], hii = sh_ii[kb];
#pragma unroll
            for (int t = 0; t < 8; t++) {
                u64 hrr_n = 0, hii_n = 0;
                if (t < 7) { hrr_n = sh_rr[kb - t - 1]; hii_n = sh_ii[kb - t - 1]; }
#pragma unroll
                for (int j = 0; j < PT; j++) {
                    accA[j] = fma2(hrr, w[(j + t) & 15], accA[j]);
                    accB[j] = fma2(hii, w[(j + t) & 15], accB[j]);
                }
                float2 v = sx[SIDX(base + l0 + 16 + t)];
                w[t & 15] = pack2(v.x, v.y);
                hrr = hrr_n; hii = hii_n;
            }
        }

        // ---- phase B: l0' = l0 + 8, mod 16 == 8 ----
        {
            const int kb = 512 - l0 - 8;
            u64 hrr = sh_rr[kb], hii = sh_ii[kb];
#pragma unroll
            for (int t = 0; t < 8; t++) {
                u64 hrr_n = 0, hii_n = 0;
                if (t < 7) { hrr_n = sh_rr[kb - t - 1]; hii_n = sh_ii[kb - t - 1]; }
#pragma unroll
                for (int j = 0; j < PT; j++) {
                    accA[j] = fma2(hrr, w[(8 + j + t) & 15], accA[j]);
                    accB[j] = fma2(hii, w[(8 + j + t) & 15], accB[j]);
                }
                float2 v = sx[SIDX(base + l0 + 24 + t)];
                w[(8 + t) & 15] = pack2(v.x, v.y);
                hrr = hrr_n; hii = hii_n;
            }
        }
    }

    // Remainder tap k = 0: offset 512 + j lives in slot (512+j)&15 = j.
    {
        u64 hrr = sh_rr[0], hii = sh_ii[0];
#pragma unroll
        for (int j = 0; j < PT; j++) {
            accA[j] = fma2(hrr, w[j], accA[j]);
            accB[j] = fma2(hii, w[j], accB[j]);
        }
    }

    // Combine: y_re = accA.lo - accB.hi, y_im = accA.hi + accB.lo.
    const int n0 = tileStart + base;
    if (n0 + PT <= NOUT) {
        float2* o = out + (size_t)pol * NOUT + n0;
#pragma unroll
        for (int j = 0; j < PT; j++) {
            float2 a = unpack2(accA[j]);
            float2 b = unpack2(accB[j]);
            o[j] = make_float2(a.x - b.y, a.y + b.x);
        }
    }
}

extern "C" void kernel_launch(void* const* d_in, const int* in_sizes, int n_in,
                              void* d_out, int out_size)
{
    const float* txr = (const float*)d_in[0];  // [2, N]
    const float* txi = (const float*)d_in[1];  // [2, N]
    const float* hre = (const float*)d_in[2];  // [L]
    const float* him = (const float*)d_in[3];  // [L]

    const int N    = in_sizes[0] / 2;
    const int L    = in_sizes[2];
    const int NOUT = N + L - 1;

    const int tiles = (NOUT + TILE - 1) / TILE;
    dim3 grid(tiles, 2);
    conv_dp_kernel<<<grid, THREADS>>>(txr, txi, hre, him, (float2*)d_out, N, NOUT);
}

// round 9
// speedup vs baseline: 3.5314x; 3.5314x over previous
#include <cuda_runtime.h>
#include <math.h>

// FixedChannelDP via overlap-save FFT convolution.
// y[p,n] = sum_k h[k] x[p,n-k], L=513 taps, output [2, NOUT, 2] f32 (float2).
//
// NF=2048-pt FFT, overlap 512 (= L-1), payload 1536 outputs/tile.
// Per tile: load 2048 samples (zero-padded), FFT, W = conj(X)*Hc where
// Hc = conj(FFT(h))/NF (precomputed by prep kernel), FFT again, y = conj(.).
// Mixed-radix Stockham (radix-2 then 5x radix-4), self-sorting, smem ping-pong.

#define NF      2048
#define OVER    512
#define PAYLOAD 1536
#define THREADS 256

// Bank-conflict padding for smem complex arrays.
#define PAD(i) ((i) + ((i) >> 3))
#define NFP    (NF + NF / 8)          // 2304
#define TWN    1024
#define TWP_N  (TWN + TWN / 8)        // 1152

__device__ float2 d_Hc[NF];   // conj(FFT_2048(h)) / 2048

__device__ __forceinline__ float2 cmul(float2 a, float2 b) {
    return make_float2(fmaf(a.x, b.x, -a.y * b.y), fmaf(a.x, b.y, a.y * b.x));
}
__device__ __forceinline__ float2 cadd(float2 a, float2 b) { return make_float2(a.x + b.x, a.y + b.y); }
__device__ __forceinline__ float2 csub(float2 a, float2 b) { return make_float2(a.x - b.x, a.y - b.y); }

// Twiddle table: TW[m] = W_2048^m = exp(-2*pi*i*m/2048), m in [0,1024).
__device__ __forceinline__ void fill_tw(float2* TW, int tid) {
    for (int m = tid; m < TWN; m += THREADS) {
        float sv, cv;
        sincosf(-6.283185307179586f * (float)m / 2048.0f, &sv, &cv);
        TW[PAD(m)] = make_float2(cv, sv);
    }
}

// Stockham radix-2 stage: l=1024, s=1.  dst[2j]=a+b, dst[2j+1]=W_2048^j*(a-b).
__device__ __forceinline__ void r2stage(const float2* src, float2* dst, const float2* tw, int tid) {
#pragma unroll
    for (int i = 0; i < 4; i++) {
        int idx = tid + THREADS * i;            // j in [0,1024)
        float2 a = src[PAD(idx)];
        float2 b = src[PAD(idx + 1024)];
        float2 w = tw[PAD(idx)];
        dst[PAD(2 * idx)]     = cadd(a, b);
        dst[PAD(2 * idx + 1)] = cmul(w, csub(a, b));
    }
}

// Stockham radix-4 stage with stride s (l*s = 512).
// idx = j*s + k;  a_q = src[idx + q*512];  b_p = DFT4(a)_p;
// dst[4*j*s + k + p*s] = W_2048^{p*j*s} * b_p.
__device__ __forceinline__ void r4stage(const float2* src, float2* dst, const float2* tw, int s, int tid) {
#pragma unroll
    for (int i = 0; i < 2; i++) {
        int idx = tid + THREADS * i;            // [0, 512)
        int k   = idx & (s - 1);
        int js  = idx - k;                      // j*s
        float2 a0 = src[PAD(idx)];
        float2 a1 = src[PAD(idx + 512)];
        float2 a2 = src[PAD(idx + 1024)];
        float2 a3 = src[PAD(idx + 1536)];
        float2 t0 = cadd(a0, a2), t1 = csub(a0, a2);
        float2 t2 = cadd(a1, a3), t3 = csub(a1, a3);
        float2 mi3 = make_float2(t3.y, -t3.x);  // -i * t3  (forward transform)
        float2 b0 = cadd(t0, t2);
        float2 b2 = csub(t0, t2);
        float2 b1 = cadd(t1, mi3);
        float2 b3 = csub(t1, mi3);
        float2 w1 = tw[PAD(js)];                // js <= 510
        float2 w2 = tw[PAD(2 * js)];            // 2*js <= 1020
        float2 w3 = cmul(w1, w2);               // 3*js may exceed table; derive
        int ob = 4 * js + k;
        dst[PAD(ob)]         = b0;
        dst[PAD(ob + s)]     = cmul(w1, b1);
        dst[PAD(ob + 2 * s)] = cmul(w2, b2);
        dst[PAD(ob + 3 * s)] = cmul(w3, b3);
    }
}

// Forward 2048-pt FFT. Input in A, result ends in A. Syncs internally.
__device__ void fft2048(float2* A, float2* B, const float2* tw, int tid) {
    r2stage(A, B, tw, tid);        __syncthreads();
    r4stage(B, A, tw, 2, tid);     __syncthreads();
    r4stage(A, B, tw, 8, tid);     __syncthreads();
    r4stage(B, A, tw, 32, tid);    __syncthreads();
    r4stage(A, B, tw, 128, tid);   __syncthreads();
    r4stage(B, A, tw, 512, tid);   __syncthreads();
}

// ---- Kernel 1: precompute Hc = conj(FFT(h)) / NF ----
__global__ void __launch_bounds__(THREADS)
prep_kernel(const float* __restrict__ hre, const float* __restrict__ him, int L)
{
    __shared__ float2 A[NFP], B[NFP], TW[TWP_N];
    int tid = threadIdx.x;
    fill_tw(TW, tid);
    for (int i = tid; i < NF; i += THREADS) {
        float2 v = make_float2(0.0f, 0.0f);
        if (i < L) v = make_float2(hre[i], him[i]);
        A[PAD(i)] = v;
    }
    __syncthreads();
    fft2048(A, B, TW, tid);
    const float sc = 1.0f / (float)NF;
    for (int i = tid; i < NF; i += THREADS) {
        float2 H = A[PAD(i)];
        d_Hc[i] = make_float2(H.x * sc, -H.y * sc);
    }
}

// ---- Kernel 2: overlap-save tiles ----
__global__ void __launch_bounds__(THREADS)
conv_fft_kernel(const float* __restrict__ txr, const float* __restrict__ txi,
                float2* __restrict__ out, int N, int NOUT)
{
    __shared__ float2 A[NFP], B[NFP], TW[TWP_N];
    const int tid = threadIdx.x;
    const int pol = blockIdx.y;
    const long segStart = (long)blockIdx.x * PAYLOAD - OVER;
    const float* __restrict__ xr = txr + (size_t)pol * N;
    const float* __restrict__ xi = txi + (size_t)pol * N;

    fill_tw(TW, tid);

    // Load segment (zero-padded outside [0, N)).
    for (int i = tid; i < NF; i += THREADS) {
        long g = segStart + i;
        float2 v = make_float2(0.0f, 0.0f);
        if (g >= 0 && g < (long)N) v = make_float2(xr[g], xi[g]);
        A[PAD(i)] = v;
    }
    __syncthreads();

    fft2048(A, B, TW, tid);        // X = FFT(x_seg), in A

    // W = conj(X) * Hc   (= conj(X .* H) / NF)
    for (int i = tid; i < NF; i += THREADS) {
        float2 x  = A[PAD(i)];
        float2 hc = d_Hc[i];
        A[PAD(i)] = make_float2(fmaf(x.x, hc.x,  x.y * hc.y),
                                fmaf(x.x, hc.y, -x.y * hc.x));
    }
    __syncthreads();

    fft2048(A, B, TW, tid);        // FFT(W); y = conj(.) = IFFT(X .* H)

    // Emit payload: outputs n = segStart + i, i in [512, 2048).
    for (int i = OVER + tid; i < NF; i += THREADS) {
        long n = segStart + i;
        if (n < (long)NOUT) {
            float2 v = A[PAD(i)];
            out[(size_t)pol * NOUT + n] = make_float2(v.x, -v.y);
        }
    }
}

extern "C" void kernel_launch(void* const* d_in, const int* in_sizes, int n_in,
                              void* d_out, int out_size)
{
    const float* txr = (const float*)d_in[0];  // [2, N]
    const float* txi = (const float*)d_in[1];  // [2, N]
    const float* hre = (const float*)d_in[2];  // [L]
    const float* him = (const float*)d_in[3];  // [L]

    const int N    = in_sizes[0] / 2;
    const int L    = in_sizes[2];              // 513 (= OVER+1; scheme requires L-1 <= OVER)
    const int NOUT = N + L - 1;

    prep_kernel<<<1, THREADS>>>(hre, him, L);

    const int tiles = (NOUT + PAYLOAD - 1) / PAYLOAD;
    dim3 grid(tiles, 2);
    conv_fft_kernel<<<grid, THREADS>>>(txr, txi, (float2*)d_out, N, NOUT);
}

// round 11
// speedup vs baseline: 4.1551x; 1.1766x over previous
#include <cuda_runtime.h>
#include <math.h>

// FixedChannelDP via overlap-save FFT convolution.
// y[p,n] = sum_k h[k] x[p,n-k], L=513 taps, output [2, NOUT, 2] f32 (float2).
//
// R10 (resubmitted after broker timeout): radix-8 Stockham (2048 = 8*8*8*4):
// 4 smem round-trips per FFT instead of 6; one twiddle LDS per butterfly
// (w2..w7 derived via register cmuls); twiddle table precomputed once into
// gmem by prep kernel (fp64 sincos).

#define NF      2048
#define OVER    512
#define PAYLOAD 1536
#define THREADS 256

#define PAD(i) ((i) + ((i) >> 3))
#define NFP    (NF + NF / 8)          // 2304 floats2 per buffer

__device__ float2 d_Hc[NF];   // conj(FFT_2048(h)) / 2048
__device__ float2 d_TW[NF];   // W_2048^m, m in [0, 2048)

__device__ __forceinline__ float2 cmul(float2 a, float2 b) {
    return make_float2(fmaf(a.x, b.x, -a.y * b.y), fmaf(a.x, b.y, a.y * b.x));
}
__device__ __forceinline__ float2 cadd(float2 a, float2 b) { return make_float2(a.x + b.x, a.y + b.y); }
__device__ __forceinline__ float2 csub(float2 a, float2 b) { return make_float2(a.x - b.x, a.y - b.y); }

// Radix-8 Stockham stage, stride s (s in {1,8,64}). One butterfly per thread.
// idx in [0,256); k = idx mod s; js = idx - k.
// a_q = src[idx + q*256];  dst[8*js + k + p*s] = W_2048^{p*js} * DFT8(a)_p.
__device__ __forceinline__ void r8stage(const float2* src, float2* dst,
                                        const float2* tw, int s, int tid) {
    const int idx = tid;
    const int k   = idx & (s - 1);
    const int js  = idx - k;

    float2 a0 = src[PAD(idx)];
    float2 a1 = src[PAD(idx + 256)];
    float2 a2 = src[PAD(idx + 512)];
    float2 a3 = src[PAD(idx + 768)];
    float2 a4 = src[PAD(idx + 1024)];
    float2 a5 = src[PAD(idx + 1280)];
    float2 a6 = src[PAD(idx + 1536)];
    float2 a7 = src[PAD(idx + 1792)];

    const float r = 0.70710678118654752440f;  // sqrt(2)/2

    float2 t0 = cadd(a0, a4), t1 = csub(a0, a4);
    float2 t2 = cadd(a2, a6), t3 = csub(a2, a6);
    float2 t4 = cadd(a1, a5), t5 = csub(a1, a5);
    float2 t6 = cadd(a3, a7), t7 = csub(a3, a7);
    float2 m3 = make_float2(t3.y, -t3.x);      // -i * t3
    float2 m7 = make_float2(t7.y, -t7.x);      // -i * t7

    float2 e0 = cadd(t0, t2), e2 = csub(t0, t2);
    float2 e1 = cadd(t1, m3), e3 = csub(t1, m3);
    float2 o0 = cadd(t4, t6), o2 = csub(t4, t6);
    float2 o1 = cadd(t5, m7), o3 = csub(t5, m7);

    // W8^1*o1, W8^2*o2, W8^3*o3
    float2 ro1 = make_float2(r * (o1.x + o1.y), r * (o1.y - o1.x));
    float2 ro2 = make_float2(o2.y, -o2.x);
    float2 ro3 = make_float2(r * (o3.y - o3.x), -r * (o3.x + o3.y));

    float2 b0 = cadd(e0, o0),  b4 = csub(e0, o0);
    float2 b1 = cadd(e1, ro1), b5 = csub(e1, ro1);
    float2 b2 = cadd(e2, ro2), b6 = csub(e2, ro2);
    float2 b3 = cadd(e3, ro3), b7 = csub(e3, ro3);

    // Output twiddles: one LDS, rest derived in registers (fma pipe).
    float2 w1 = tw[PAD(js)];
    float2 w2 = cmul(w1, w1);
    float2 w3 = cmul(w2, w1);
    float2 w4 = cmul(w2, w2);
    float2 w5 = cmul(w3, w2);
    float2 w6 = cmul(w3, w3);
    float2 w7 = cmul(w4, w3);

    const int ob = 8 * js + k;
    dst[PAD(ob)]         = b0;
    dst[PAD(ob + s)]     = cmul(w1, b1);
    dst[PAD(ob + 2 * s)] = cmul(w2, b2);
    dst[PAD(ob + 3 * s)] = cmul(w3, b3);
    dst[PAD(ob + 4 * s)] = cmul(w4, b4);
    dst[PAD(ob + 5 * s)] = cmul(w5, b5);
    dst[PAD(ob + 6 * s)] = cmul(w6, b6);
    dst[PAD(ob + 7 * s)] = cmul(w7, b7);
}

// Final radix-4 stage, s = 512, l = 1: js = 0 -> twiddle-free.
// idx in [0,512), two butterflies per thread.
__device__ __forceinline__ void r4final(const float2* src, float2* dst, int tid) {
#pragma unroll
    for (int i = 0; i < 2; i++) {
        const int idx = tid + THREADS * i;
        float2 a0 = src[PAD(idx)];
        float2 a1 = src[PAD(idx + 512)];
        float2 a2 = src[PAD(idx + 1024)];
        float2 a3 = src[PAD(idx + 1536)];
        float2 t0 = cadd(a0, a2), t1 = csub(a0, a2);
        float2 t2 = cadd(a1, a3), t3 = csub(a1, a3);
        float2 mi3 = make_float2(t3.y, -t3.x);   // -i * t3
        dst[PAD(idx)]        = cadd(t0, t2);
        dst[PAD(idx + 512)]  = cadd(t1, mi3);
        dst[PAD(idx + 1024)] = csub(t0, t2);
        dst[PAD(idx + 1536)] = csub(t1, mi3);
    }
}

// Forward 2048-pt FFT. Input in A, result ends in A. Syncs internally.
__device__ void fft2048(float2* A, float2* B, const float2* tw, int tid) {
    r8stage(A, B, tw, 1,  tid);  __syncthreads();
    r8stage(B, A, tw, 8,  tid);  __syncthreads();
    r8stage(A, B, tw, 64, tid);  __syncthreads();
    r4final(B, A, tid);          __syncthreads();
}

// ---- Kernel 1: precompute d_TW and Hc = conj(FFT(h)) / NF ----
__global__ void __launch_bounds__(THREADS)
prep_kernel(const float* __restrict__ hre, const float* __restrict__ him, int L)
{
    __shared__ float2 A[NFP], B[NFP], TW[NFP];
    int tid = threadIdx.x;
    for (int m = tid; m < NF; m += THREADS) {
        double sv, cv;
        sincos(-6.283185307179586476925287 * (double)m / (double)NF, &sv, &cv);
        float2 w = make_float2((float)cv, (float)sv);
        TW[PAD(m)] = w;
        d_TW[m] = w;
    }
    for (int i = tid; i < NF; i += THREADS) {
        float2 v = make_float2(0.0f, 0.0f);
        if (i < L) v = make_float2(hre[i], him[i]);
        A[PAD(i)] = v;
    }
    __syncthreads();
    fft2048(A, B, TW, tid);
    const float sc = 1.0f / (float)NF;
    for (int i = tid; i < NF; i += THREADS) {
        float2 H = A[PAD(i)];
        d_Hc[i] = make_float2(H.x * sc, -H.y * sc);
    }
}

// ---- Kernel 2: overlap-save tiles ----
__global__ void __launch_bounds__(THREADS, 3)
conv_fft_kernel(const float* __restrict__ txr, const float* __restrict__ txi,
                float2* __restrict__ out, int N, int NOUT)
{
    __shared__ float2 A[NFP], B[NFP], TW[NFP];
    const int tid = threadIdx.x;
    const int pol = blockIdx.y;
    const long segStart = (long)blockIdx.x * PAYLOAD - OVER;
    const float* __restrict__ xr = txr + (size_t)pol * N;
    const float* __restrict__ xi = txi + (size_t)pol * N;

    // Twiddle table from gmem (L2-resident), coalesced.
    for (int m = tid; m < NF; m += THREADS) TW[PAD(m)] = d_TW[m];

    // Load segment (zero-padded outside [0, N)).
    for (int i = tid; i < NF; i += THREADS) {
        long g = segStart + i;
        float2 v = make_float2(0.0f, 0.0f);
        if (g >= 0 && g < (long)N) v = make_float2(xr[g], xi[g]);
        A[PAD(i)] = v;
    }
    __syncthreads();

    fft2048(A, B, TW, tid);        // X = FFT(x_seg), in A

    // W = conj(X) * Hc   (= conj(X .* H) / NF)
    for (int i = tid; i < NF; i += THREADS) {
        float2 x  = A[PAD(i)];
        float2 hc = d_Hc[i];
        A[PAD(i)] = make_float2(fmaf(x.x, hc.x,  x.y * hc.y),
                                fmaf(x.x, hc.y, -x.y * hc.x));
    }
    __syncthreads();

    fft2048(A, B, TW, tid);        // FFT(W); y = conj(.) = IFFT(X .* H)

    // Emit payload: outputs n = segStart + i, i in [512, 2048).
    for (int i = OVER + tid; i < NF; i += THREADS) {
        long n = segStart + i;
        if (n < (long)NOUT) {
            float2 v = A[PAD(i)];
            out[(size_t)pol * NOUT + n] = make_float2(v.x, -v.y);
        }
    }
}

extern "C" void kernel_launch(void* const* d_in, const int* in_sizes, int n_in,
                              void* d_out, int out_size)
{
    const float* txr = (const float*)d_in[0];  // [2, N]
    const float* txi = (const float*)d_in[1];  // [2, N]
    const float* hre = (const float*)d_in[2];  // [L]
    const float* him = (const float*)d_in[3];  // [L]

    const int N    = in_sizes[0] / 2;
    const int L    = in_sizes[2];              // 513 (scheme requires L-1 <= OVER)
    const int NOUT = N + L - 1;

    prep_kernel<<<1, THREADS>>>(hre, him, L);

    const int tiles = (NOUT + PAYLOAD - 1) / PAYLOAD;
    dim3 grid(tiles, 2);
    conv_fft_kernel<<<grid, THREADS>>>(txr, txi, (float2*)d_out, N, NOUT);
}

// round 13
// speedup vs baseline: 7.4738x; 1.7987x over previous
#include <cuda_runtime.h>
#include <math.h>

// FixedChannelDP via overlap-save FFT convolution (fused-I/O radix-8 Stockham).
// y[p,n] = sum_k h[k] x[p,n-k], L=513 taps, output [2, NOUT, 2] f32 (float2).
//
// R12 (resubmitted after container failure): all staging fused into FFT stages.
//  FFT1 stage1 reads gmem x directly; FFT1 final radix-4 fuses conj(X)*Hc;
//  FFT2 final radix-4 writes conj() results straight to gmem (skips discard
//  region); twiddles via one LDG/butterfly from L2-resident d_TW (no smem TW);
//  prep split into parallel tw_kernel + 1-CTA hc_kernel.

#define NF      2048
#define OVER    512
#define PAYLOAD 1536
#define THREADS 256

#define PAD(i) ((i) + ((i) >> 3))
#define NFP    (NF + NF / 8)          // 2304 float2 per buffer

__device__ float2 d_Hc[NF];   // conj(FFT_2048(h)) / 2048
__device__ float2 d_TW[NF];   // W_2048^m

__device__ __forceinline__ float2 cmul(float2 a, float2 b) {
    return make_float2(fmaf(a.x, b.x, -a.y * b.y), fmaf(a.x, b.y, a.y * b.x));
}
__device__ __forceinline__ float2 cadd(float2 a, float2 b) { return make_float2(a.x + b.x, a.y + b.y); }
__device__ __forceinline__ float2 csub(float2 a, float2 b) { return make_float2(a.x - b.x, a.y - b.y); }
// conj(x) * h
__device__ __forceinline__ float2 conjmul(float2 x, float2 h) {
    return make_float2(fmaf(x.x, h.x, x.y * h.y), fmaf(x.x, h.y, -x.y * h.x));
}

// In-register DFT-8. a[0..7] -> transformed in natural order.
__device__ __forceinline__ void dft8(float2* a) {
    const float r = 0.70710678118654752440f;
    float2 t0 = cadd(a[0], a[4]), t1 = csub(a[0], a[4]);
    float2 t2 = cadd(a[2], a[6]), t3 = csub(a[2], a[6]);
    float2 t4 = cadd(a[1], a[5]), t5 = csub(a[1], a[5]);
    float2 t6 = cadd(a[3], a[7]), t7 = csub(a[3], a[7]);
    float2 m3 = make_float2(t3.y, -t3.x);
    float2 m7 = make_float2(t7.y, -t7.x);
    float2 e0 = cadd(t0, t2), e2 = csub(t0, t2);
    float2 e1 = cadd(t1, m3), e3 = csub(t1, m3);
    float2 o0 = cadd(t4, t6), o2 = csub(t4, t6);
    float2 o1 = cadd(t5, m7), o3 = csub(t5, m7);
    float2 ro1 = make_float2(r * (o1.x + o1.y), r * (o1.y - o1.x));
    float2 ro2 = make_float2(o2.y, -o2.x);
    float2 ro3 = make_float2(r * (o3.y - o3.x), -r * (o3.x + o3.y));
    a[0] = cadd(e0, o0);  a[4] = csub(e0, o0);
    a[1] = cadd(e1, ro1); a[5] = csub(e1, ro1);
    a[2] = cadd(e2, ro2); a[6] = csub(e2, ro2);
    a[3] = cadd(e3, ro3); a[7] = csub(e3, ro3);
}

// Twiddle chain + scatter for a radix-8 stage (stride s, base js, offset k).
__device__ __forceinline__ void r8_scatter(float2* dst, const float2* a, int js, int k, int s) {
    float2 w1 = d_TW[js];
    float2 w2 = cmul(w1, w1);
    float2 w3 = cmul(w2, w1);
    float2 w4 = cmul(w2, w2);
    float2 w5 = cmul(w3, w2);
    float2 w6 = cmul(w3, w3);
    float2 w7 = cmul(w4, w3);
    const int ob = 8 * js + k;
    dst[PAD(ob)]         = a[0];
    dst[PAD(ob + s)]     = cmul(w1, a[1]);
    dst[PAD(ob + 2 * s)] = cmul(w2, a[2]);
    dst[PAD(ob + 3 * s)] = cmul(w3, a[3]);
    dst[PAD(ob + 4 * s)] = cmul(w4, a[4]);
    dst[PAD(ob + 5 * s)] = cmul(w5, a[5]);
    dst[PAD(ob + 6 * s)] = cmul(w6, a[6]);
    dst[PAD(ob + 7 * s)] = cmul(w7, a[7]);
}

// smem -> smem radix-8 stage (s in {1, 8, 64}).
__device__ __forceinline__ void r8_s2s(const float2* src, float2* dst, int s, int tid) {
    const int k = tid & (s - 1);
    const int js = tid - k;
    float2 a[8];
#pragma unroll
    for (int q = 0; q < 8; q++) a[q] = src[PAD(tid + q * 256)];
    dft8(a);
    r8_scatter(dst, a, js, k, s);
}

// gmem -> smem radix-8 first stage (s = 1), zero-padded segment load fused.
__device__ __forceinline__ void r8_g2s(const float* __restrict__ xr, const float* __restrict__ xi,
                                       long segStart, int Nn, float2* dst, int tid) {
    float2 a[8];
#pragma unroll
    for (int q = 0; q < 8; q++) {
        long g = segStart + tid + q * 256;
        float2 v = make_float2(0.0f, 0.0f);
        if (g >= 0 && g < (long)Nn) v = make_float2(xr[g], xi[g]);
        a[q] = v;
    }
    dft8(a);
    r8_scatter(dst, a, tid, 0, 1);
}

// Final radix-4 of FFT1 (s=512, twiddle-free), fused with W = conj(X)*Hc.
__device__ __forceinline__ void r4_hc(const float2* src, float2* dst, int tid) {
#pragma unroll
    for (int i = 0; i < 2; i++) {
        const int idx = tid + THREADS * i;
        float2 a0 = src[PAD(idx)];
        float2 a1 = src[PAD(idx + 512)];
        float2 a2 = src[PAD(idx + 1024)];
        float2 a3 = src[PAD(idx + 1536)];
        float2 t0 = cadd(a0, a2), t1 = csub(a0, a2);
        float2 t2 = cadd(a1, a3), t3 = csub(a1, a3);
        float2 mi3 = make_float2(t3.y, -t3.x);
        dst[PAD(idx)]        = conjmul(cadd(t0, t2),  d_Hc[idx]);
        dst[PAD(idx + 512)]  = conjmul(cadd(t1, mi3), d_Hc[idx + 512]);
        dst[PAD(idx + 1024)] = conjmul(csub(t0, t2),  d_Hc[idx + 1024]);
        dst[PAD(idx + 1536)] = conjmul(csub(t1, mi3), d_Hc[idx + 1536]);
    }
}

// Final radix-4 of FFT2, fused with conj() and gmem store of the payload.
// Output index idx (<512) falls in the overlap/discard region -> skipped.
__device__ __forceinline__ void r4_out(const float2* src, float2* __restrict__ outp,
                                       long segStart, int NOUT, int tid) {
#pragma unroll
    for (int i = 0; i < 2; i++) {
        const int idx = tid + THREADS * i;
        float2 a0 = src[PAD(idx)];
        float2 a1 = src[PAD(idx + 512)];
        float2 a2 = src[PAD(idx + 1024)];
        float2 a3 = src[PAD(idx + 1536)];
        float2 t0 = cadd(a0, a2), t1 = csub(a0, a2);
        float2 t2 = cadd(a1, a3), t3 = csub(a1, a3);
        float2 mi3 = make_float2(t3.y, -t3.x);
        float2 X1 = cadd(t1, mi3);
        float2 X2 = csub(t0, t2);
        float2 X3 = csub(t1, mi3);
        long n1 = segStart + idx + 512;
        long n2 = segStart + idx + 1024;
        long n3 = segStart + idx + 1536;
        if (n1 < (long)NOUT) outp[n1] = make_float2(X1.x, -X1.y);
        if (n2 < (long)NOUT) outp[n2] = make_float2(X2.x, -X2.y);
        if (n3 < (long)NOUT) outp[n3] = make_float2(X3.x, -X3.y);
    }
}

// ---- Prep kernel 1: twiddle table (parallel, fp64-accurate) ----
__global__ void tw_kernel() {
    int m = blockIdx.x * THREADS + threadIdx.x;
    if (m < NF) {
        double sv, cv;
        sincos(-6.283185307179586476925287 * (double)m / (double)NF, &sv, &cv);
        d_TW[m] = make_float2((float)cv, (float)sv);
    }
}

// ---- Prep kernel 2: Hc = conj(FFT(h)) / NF (1 CTA; runs after tw_kernel) ----
__global__ void __launch_bounds__(THREADS)
hc_kernel(const float* __restrict__ hre, const float* __restrict__ him, int L)
{
    __shared__ float2 A[NFP], B[NFP];
    const int tid = threadIdx.x;
    for (int i = tid; i < NF; i += THREADS) {
        float2 v = make_float2(0.0f, 0.0f);
        if (i < L) v = make_float2(hre[i], him[i]);
        A[PAD(i)] = v;
    }
    __syncthreads();
    r8_s2s(A, B, 1,  tid); __syncthreads();
    r8_s2s(B, A, 8,  tid); __syncthreads();
    r8_s2s(A, B, 64, tid); __syncthreads();
    const float sc = 1.0f / (float)NF;
#pragma unroll
    for (int i = 0; i < 2; i++) {
        const int idx = tid + THREADS * i;
        float2 a0 = B[PAD(idx)];
        float2 a1 = B[PAD(idx + 512)];
        float2 a2 = B[PAD(idx + 1024)];
        float2 a3 = B[PAD(idx + 1536)];
        float2 t0 = cadd(a0, a2), t1 = csub(a0, a2);
        float2 t2 = cadd(a1, a3), t3 = csub(a1, a3);
        float2 mi3 = make_float2(t3.y, -t3.x);
        float2 X0 = cadd(t0, t2), X1 = cadd(t1, mi3);
        float2 X2 = csub(t0, t2), X3 = csub(t1, mi3);
        d_Hc[idx]        = make_float2(X0.x * sc, -X0.y * sc);
        d_Hc[idx + 512]  = make_float2(X1.x * sc, -X1.y * sc);
        d_Hc[idx + 1024] = make_float2(X2.x * sc, -X2.y * sc);
        d_Hc[idx + 1536] = make_float2(X3.x * sc, -X3.y * sc);
    }
}

// ---- Main kernel: overlap-save tile, fully fused ----
__global__ void __launch_bounds__(THREADS, 4)
conv_fft_kernel(const float* __restrict__ txr, const float* __restrict__ txi,
                float2* __restrict__ out, int N, int NOUT)
{
    __shared__ float2 A[NFP], B[NFP];
    const int tid = threadIdx.x;
    const int pol = blockIdx.y;
    const long segStart = (long)blockIdx.x * PAYLOAD - OVER;
    const float* __restrict__ xr = txr + (size_t)pol * N;
    const float* __restrict__ xi = txi + (size_t)pol * N;

    // FFT1 (gmem in, Hc multiply fused at the end)
    r8_g2s(xr, xi, segStart, N, B, tid); __syncthreads();
    r8_s2s(B, A, 8,  tid);               __syncthreads();
    r8_s2s(A, B, 64, tid);               __syncthreads();
    r4_hc(B, A, tid);                    __syncthreads();
    // FFT2 (gmem out with conj fused at the end)
    r8_s2s(A, B, 1,  tid);               __syncthreads();
    r8_s2s(B, A, 8,  tid);               __syncthreads();
    r8_s2s(A, B, 64, tid);               __syncthreads();
    r4_out(B, out + (size_t)pol * NOUT, segStart, NOUT, tid);
}

extern "C" void kernel_launch(void* const* d_in, const int* in_sizes, int n_in,
                              void* d_out, int out_size)
{
    const float* txr = (const float*)d_in[0];  // [2, N]
    const float* txi = (const float*)d_in[1];  // [2, N]
    const float* hre = (const float*)d_in[2];  // [L]
    const float* him = (const float*)d_in[3];  // [L]

    const int N    = in_sizes[0] / 2;
    const int L    = in_sizes[2];              // 513 (scheme requires L-1 <= OVER)
    const int NOUT = N + L - 1;

    tw_kernel<<<(NF + THREADS - 1) / THREADS, THREADS>>>();
    hc_kernel<<<1, THREADS>>>(hre, him, L);

    const int tiles = (NOUT + PAYLOAD - 1) / PAYLOAD;
    dim3 grid(tiles, 2);
    conv_fft_kernel<<<grid, THREADS>>>(txr, txi, (float2*)d_out, N, NOUT);
}

// round 14
// speedup vs baseline: 8.4983x; 1.1371x over previous
#include <cuda_runtime.h>
#include <math.h>

// FixedChannelDP via overlap-save FFT convolution (fused-I/O radix-8 Stockham).
// y[p,n] = sum_k h[k] x[p,n-k], L=513 taps, output [2, NOUT, 2] f32 (float2).
//
// R14:
//  - prep merged into ONE kernel (twiddles via sincospif, then h-FFT).
//  - FFT1 final radix-4 (+Hc multiply) fused in registers with FFT2's first
//    radix-8: thread tid holds exactly W[tid + q*256] after the r4 -> no smem
//    round trip, one fewer barrier (7 -> 6 stage passes).

#define NF      2048
#define OVER    512
#define PAYLOAD 1536
#define THREADS 256

#define PAD(i) ((i) + ((i) >> 3))
#define NFP    (NF + NF / 8)          // 2304 float2 per buffer

__device__ float2 d_Hc[NF];   // conj(FFT_2048(h)) / 2048
__device__ float2 d_TW[NF];   // W_2048^m

__device__ __forceinline__ float2 cmul(float2 a, float2 b) {
    return make_float2(fmaf(a.x, b.x, -a.y * b.y), fmaf(a.x, b.y, a.y * b.x));
}
__device__ __forceinline__ float2 cadd(float2 a, float2 b) { return make_float2(a.x + b.x, a.y + b.y); }
__device__ __forceinline__ float2 csub(float2 a, float2 b) { return make_float2(a.x - b.x, a.y - b.y); }
// conj(x) * h
__device__ __forceinline__ float2 conjmul(float2 x, float2 h) {
    return make_float2(fmaf(x.x, h.x, x.y * h.y), fmaf(x.x, h.y, -x.y * h.x));
}

// In-register DFT-8. a[0..7] -> transformed in natural order.
__device__ __forceinline__ void dft8(float2* a) {
    const float r = 0.70710678118654752440f;
    float2 t0 = cadd(a[0], a[4]), t1 = csub(a[0], a[4]);
    float2 t2 = cadd(a[2], a[6]), t3 = csub(a[2], a[6]);
    float2 t4 = cadd(a[1], a[5]), t5 = csub(a[1], a[5]);
    float2 t6 = cadd(a[3], a[7]), t7 = csub(a[3], a[7]);
    float2 m3 = make_float2(t3.y, -t3.x);
    float2 m7 = make_float2(t7.y, -t7.x);
    float2 e0 = cadd(t0, t2), e2 = csub(t0, t2);
    float2 e1 = cadd(t1, m3), e3 = csub(t1, m3);
    float2 o0 = cadd(t4, t6), o2 = csub(t4, t6);
    float2 o1 = cadd(t5, m7), o3 = csub(t5, m7);
    float2 ro1 = make_float2(r * (o1.x + o1.y), r * (o1.y - o1.x));
    float2 ro2 = make_float2(o2.y, -o2.x);
    float2 ro3 = make_float2(r * (o3.y - o3.x), -r * (o3.x + o3.y));
    a[0] = cadd(e0, o0);  a[4] = csub(e0, o0);
    a[1] = cadd(e1, ro1); a[5] = csub(e1, ro1);
    a[2] = cadd(e2, ro2); a[6] = csub(e2, ro2);
    a[3] = cadd(e3, ro3); a[7] = csub(e3, ro3);
}

// Twiddle chain + scatter for a radix-8 stage (stride s, base js, offset k).
__device__ __forceinline__ void r8_scatter(float2* dst, const float2* a, int js, int k, int s) {
    float2 w1 = d_TW[js];
    float2 w2 = cmul(w1, w1);
    float2 w3 = cmul(w2, w1);
    float2 w4 = cmul(w2, w2);
    float2 w5 = cmul(w3, w2);
    float2 w6 = cmul(w3, w3);
    float2 w7 = cmul(w4, w3);
    const int ob = 8 * js + k;
    dst[PAD(ob)]         = a[0];
    dst[PAD(ob + s)]     = cmul(w1, a[1]);
    dst[PAD(ob + 2 * s)] = cmul(w2, a[2]);
    dst[PAD(ob + 3 * s)] = cmul(w3, a[3]);
    dst[PAD(ob + 4 * s)] = cmul(w4, a[4]);
    dst[PAD(ob + 5 * s)] = cmul(w5, a[5]);
    dst[PAD(ob + 6 * s)] = cmul(w6, a[6]);
    dst[PAD(ob + 7 * s)] = cmul(w7, a[7]);
}

// smem -> smem radix-8 stage (s in {1, 8, 64}).
__device__ __forceinline__ void r8_s2s(const float2* src, float2* dst, int s, int tid) {
    const int k = tid & (s - 1);
    const int js = tid - k;
    float2 a[8];
#pragma unroll
    for (int q = 0; q < 8; q++) a[q] = src[PAD(tid + q * 256)];
    dft8(a);
    r8_scatter(dst, a, js, k, s);
}

// gmem -> smem radix-8 first stage (s = 1), zero-padded segment load fused.
__device__ __forceinline__ void r8_g2s(const float* __restrict__ xr, const float* __restrict__ xi,
                                       long segStart, int Nn, float2* dst, int tid) {
    float2 a[8];
#pragma unroll
    for (int q = 0; q < 8; q++) {
        long g = segStart + tid + q * 256;
        float2 v = make_float2(0.0f, 0.0f);
        if (g >= 0 && g < (long)Nn) v = make_float2(xr[g], xi[g]);
        a[q] = v;
    }
    dft8(a);
    r8_scatter(dst, a, tid, 0, 1);
}

// FUSED: FFT1 final radix-4 (twiddle-free, s=512) + W = conj(X)*Hc + FFT2
// first radix-8 (s=1). Thread tid's two r4 butterflies (idx=tid, tid+256)
// produce exactly W[tid + q*256], q=0..7 -> feed dft8 directly. One smem
// round trip and one barrier eliminated.
__device__ __forceinline__ void r4hc_r8_fused(const float2* src, float2* dst, int tid) {
    float2 a[8];
#pragma unroll
    for (int i = 0; i < 2; i++) {
        const int idx = tid + 256 * i;
        float2 b0 = src[PAD(idx)];
        float2 b1 = src[PAD(idx + 512)];
        float2 b2 = src[PAD(idx + 1024)];
        float2 b3 = src[PAD(idx + 1536)];
        float2 t0 = cadd(b0, b2), t1 = csub(b0, b2);
        float2 t2 = cadd(b1, b3), t3 = csub(b1, b3);
        float2 mi3 = make_float2(t3.y, -t3.x);
        a[0 + i] = conjmul(cadd(t0, t2),  d_Hc[idx]);          // W[idx]
        a[2 + i] = conjmul(cadd(t1, mi3), d_Hc[idx + 512]);    // W[idx+512]
        a[4 + i] = conjmul(csub(t0, t2),  d_Hc[idx + 1024]);   // W[idx+1024]
        a[6 + i] = conjmul(csub(t1, mi3), d_Hc[idx + 1536]);   // W[idx+1536]
    }
    dft8(a);
    r8_scatter(dst, a, tid, 0, 1);
}

// Final radix-4 of FFT2, fused with conj() and gmem store of the payload.
// Output index idx (<512) falls in the overlap/discard region -> skipped.
__device__ __forceinline__ void r4_out(const float2* src, float2* __restrict__ outp,
                                       long segStart, int NOUT, int tid) {
#pragma unroll
    for (int i = 0; i < 2; i++) {
        const int idx = tid + THREADS * i;
        float2 a0 = src[PAD(idx)];
        float2 a1 = src[PAD(idx + 512)];
        float2 a2 = src[PAD(idx + 1024)];
        float2 a3 = src[PAD(idx + 1536)];
        float2 t0 = cadd(a0, a2), t1 = csub(a0, a2);
        float2 t2 = cadd(a1, a3), t3 = csub(a1, a3);
        float2 mi3 = make_float2(t3.y, -t3.x);
        float2 X1 = cadd(t1, mi3);
        float2 X2 = csub(t0, t2);
        float2 X3 = csub(t1, mi3);
        long n1 = segStart + idx + 512;
        long n2 = segStart + idx + 1024;
        long n3 = segStart + idx + 1536;
        if (n1 < (long)NOUT) outp[n1] = make_float2(X1.x, -X1.y);
        if (n2 < (long)NOUT) outp[n2] = make_float2(X2.x, -X2.y);
        if (n3 < (long)NOUT) outp[n3] = make_float2(X3.x, -X3.y);
    }
}

// ---- Prep (single kernel, 1 CTA): twiddles then Hc = conj(FFT(h)) / NF ----
__global__ void __launch_bounds__(THREADS)
prep_kernel(const float* __restrict__ hre, const float* __restrict__ him, int L)
{
    __shared__ float2 A[NFP], B[NFP];
    const int tid = threadIdx.x;

    // Twiddles: W_2048^m = exp(-i*pi*m/1024), exact fp32 argument.
    for (int m = tid; m < NF; m += THREADS) {
        float sv, cv;
        sincospif(-(float)m / 1024.0f, &sv, &cv);
        d_TW[m] = make_float2(cv, sv);
    }
    for (int i = tid; i < NF; i += THREADS) {
        float2 v = make_float2(0.0f, 0.0f);
        if (i < L) v = make_float2(hre[i], him[i]);
        A[PAD(i)] = v;
    }
    __syncthreads();   // orders d_TW (global) and A (shared) within the CTA

    r8_s2s(A, B, 1,  tid); __syncthreads();
    r8_s2s(B, A, 8,  tid); __syncthreads();
    r8_s2s(A, B, 64, tid); __syncthreads();
    const float sc = 1.0f / (float)NF;
#pragma unroll
    for (int i = 0; i < 2; i++) {
        const int idx = tid + THREADS * i;
        float2 a0 = B[PAD(idx)];
        float2 a1 = B[PAD(idx + 512)];
        float2 a2 = B[PAD(idx + 1024)];
        float2 a3 = B[PAD(idx + 1536)];
        float2 t0 = cadd(a0, a2), t1 = csub(a0, a2);
        float2 t2 = cadd(a1, a3), t3 = csub(a1, a3);
        float2 mi3 = make_float2(t3.y, -t3.x);
        float2 X0 = cadd(t0, t2), X1 = cadd(t1, mi3);
        float2 X2 = csub(t0, t2), X3 = csub(t1, mi3);
        d_Hc[idx]        = make_float2(X0.x * sc, -X0.y * sc);
        d_Hc[idx + 512]  = make_float2(X1.x * sc, -X1.y * sc);
        d_Hc[idx + 1024] = make_float2(X2.x * sc, -X2.y * sc);
        d_Hc[idx + 1536] = make_float2(X3.x * sc, -X3.y * sc);
    }
}

// ---- Main kernel: overlap-save tile, fully fused ----
__global__ void __launch_bounds__(THREADS, 3)
conv_fft_kernel(const float* __restrict__ txr, const float* __restrict__ txi,
                float2* __restrict__ out, int N, int NOUT)
{
    __shared__ float2 A[NFP], B[NFP];
    const int tid = threadIdx.x;
    const int pol = blockIdx.y;
    const long segStart = (long)blockIdx.x * PAYLOAD - OVER;
    const float* __restrict__ xr = txr + (size_t)pol * N;
    const float* __restrict__ xi = txi + (size_t)pol * N;

    // FFT1 (gmem in)
    r8_g2s(xr, xi, segStart, N, B, tid); __syncthreads();
    r8_s2s(B, A, 8,  tid);               __syncthreads();
    r8_s2s(A, B, 64, tid);               __syncthreads();
    // FFT1 final r4 + Hc + FFT2 first r8, fused in registers
    r4hc_r8_fused(B, A, tid);            __syncthreads();
    // FFT2 remainder (gmem out with conj fused at the end)
    r8_s2s(A, B, 8,  tid);               __syncthreads();
    r8_s2s(B, A, 64, tid);               __syncthreads();
    r4_out(A, out + (size_t)pol * NOUT, segStart, NOUT, tid);
}

extern "C" void kernel_launch(void* const* d_in, const int* in_sizes, int n_in,
                              void* d_out, int out_size)
{
    const float* txr = (const float*)d_in[0];  // [2, N]
    const float* txi = (const float*)d_in[1];  // [2, N]
    const float* hre = (const float*)d_in[2];  // [L]
    const float* him = (const float*)d_in[3];  // [L]

    const int N    = in_sizes[0] / 2;
    const int L    = in_sizes[2];              // 513 (scheme requires L-1 <= OVER)
    const int NOUT = N + L - 1;

    prep_kernel<<<1, THREADS>>>(hre, him, L);

    const int tiles = (NOUT + PAYLOAD - 1) / PAYLOAD;
    dim3 grid(tiles, 2);
    conv_fft_kernel<<<grid, THREADS>>>(txr, txi, (float2*)d_out, N, NOUT);
}